// round 14
// baseline (speedup 1.0000x reference)
#include <cuda_runtime.h>
#include <cuda_fp16.h>
#include <math.h>
#include <stdint.h>

#define BATCH 64
#define SEQ   512
#define DM    512
#define NH    8
#define HD    64
#define WIN   64
#define NA    32
#define FF    2048
#define MROWS (BATCH*SEQ)     // 32768
#define MAROWS (BATCH*NA)     // 2048

// ---------------- scratch ----------------
__device__ float g_qkv[(size_t)MROWS * 3 * DM];
__device__ float g_x1 [(size_t)MROWS * DM];
__device__ float g_q2 [(size_t)MROWS * DM];
__device__ float g_kv2[(size_t)MAROWS * 2 * DM];
__device__ float g_x2 [(size_t)MROWS * DM];
__device__ float g_x3 [(size_t)MROWS * DM];
// fp16 buffers
__device__ __half g_xh   [(size_t)MROWS * DM];
__device__ __half g_anchh[(size_t)MAROWS * DM];
__device__ __half g_attnh[(size_t)MROWS * DM];
__device__ __half g_x1h  [(size_t)MROWS * DM];
__device__ __half g_x3h  [(size_t)MROWS * DM];
__device__ __half g_hh   [(size_t)MROWS * FF];
// fp16 weights, packed
#define SZ_LWIN  786432
#define SZ_LWOUT 262144
#define SZ_GWIN  786432
#define SZ_GWOUT 262144
#define SZ_W1    1048576
#define SZ_W2    1048576
#define OFF_LWIN  0
#define OFF_LWOUT (OFF_LWIN + SZ_LWIN)
#define OFF_GWIN  (OFF_LWOUT + SZ_LWOUT)
#define OFF_GWOUT (OFF_GWIN + SZ_GWIN)
#define OFF_W1    (OFF_GWOUT + SZ_GWOUT)
#define OFF_W2    (OFF_W1 + SZ_W1)
#define WTF_TOTAL (OFF_W2 + SZ_W2)
#define ANCH_N    (MAROWS * DM)
__device__ __half g_wth[(size_t)WTF_TOTAL];

// ================= helpers =================
__device__ __forceinline__ uint32_t smem_u32(const void* p) {
    uint32_t a;
    asm("{ .reg .u64 t; cvta.to.shared.u64 t, %1; cvt.u32.u64 %0, t; }" : "=r"(a) : "l"(p));
    return a;
}
__device__ __forceinline__ void mma16(float* c, const uint32_t* a, const uint32_t* b) {
    asm volatile(
        "mma.sync.aligned.m16n8k16.row.col.f32.f16.f16.f32 "
        "{%0,%1,%2,%3}, {%4,%5,%6,%7}, {%8,%9}, {%0,%1,%2,%3};"
        : "+f"(c[0]), "+f"(c[1]), "+f"(c[2]), "+f"(c[3])
        : "r"(a[0]), "r"(a[1]), "r"(a[2]), "r"(a[3]),
          "r"(b[0]), "r"(b[1]));
}
#define LDSM_X4(r0, r1, r2, r3, addr) \
    asm volatile("ldmatrix.sync.aligned.m8n8.x4.shared.b16 {%0,%1,%2,%3}, [%4];" \
        : "=r"(r0), "=r"(r1), "=r"(r2), "=r"(r3) : "r"(addr))
#define CP_ASYNC16(dst, src) \
    asm volatile("cp.async.cg.shared.global [%0], [%1], 16;" :: "r"(dst), "l"(src) : "memory")
#define CP_COMMIT() asm volatile("cp.async.commit_group;" ::: "memory")
#define CP_WAIT1()  asm volatile("cp.async.wait_group 1;" ::: "memory")

// ---------------- weight + anchor fp16 pre-convert (one launch) --------
__global__ __launch_bounds__(256)
void cvt_all(const float* __restrict__ lw_in, const float* __restrict__ lw_out,
             const float* __restrict__ gw_in, const float* __restrict__ gw_out,
             const float* __restrict__ w1, const float* __restrict__ w2,
             const float* __restrict__ anch,
             __half* __restrict__ dst, __half* __restrict__ anch_h)
{
    int i = blockIdx.x * 256 + threadIdx.x;
    if (i >= WTF_TOTAL + ANCH_N) return;
    if (i >= WTF_TOTAL) {
        anch_h[i - WTF_TOTAL] = __float2half_rn(anch[i - WTF_TOTAL]);
        return;
    }
    const float* src;
    int local;
    if      (i < OFF_LWOUT) { src = lw_in;  local = i - OFF_LWIN; }
    else if (i < OFF_GWIN)  { src = lw_out; local = i - OFF_LWOUT; }
    else if (i < OFF_GWOUT) { src = gw_in;  local = i - OFF_GWIN; }
    else if (i < OFF_W1)    { src = gw_out; local = i - OFF_GWOUT; }
    else if (i < OFF_W2)    { src = w1;     local = i - OFF_W1; }
    else                    { src = w2;     local = i - OFF_W2; }
    dst[i] = __float2half_rn(src[local]);
}

// ---------------- vectorized f32 -> f16 (for x) ----------------
__global__ __launch_bounds__(256)
void cvt4(const float* __restrict__ src, __half* __restrict__ dst, int n4)
{
    int i = blockIdx.x * 256 + threadIdx.x;
    if (i < n4) {
        float4 v = ((const float4*)src)[i];
        ((__half2*)dst)[i * 2]     = __floats2half2_rn(v.x, v.y);
        ((__half2*)dst)[i * 2 + 1] = __floats2half2_rn(v.z, v.w);
    }
}

// ================= fp16 GEMM: 3-stage cp.async pipeline =====================
// CTA tile 128x128, BK=64 halves, warp tile 64x32 (2x4 warps), 2 CTAs/SM.
// OMODE: 0 = f32 out, 1 = f16 out, 2 = both.
#define ROWW 36
#define TILE_W (128 * ROWW)               // 4608 words per tile buffer
#define GEMM_SMEM_W (6 * TILE_W)          // A0..A2 B0..B2 = 110592 B

template<bool GELU, int OMODE>
__global__ __launch_bounds__(256, 2)
void gemm_hh(const __half* __restrict__ A, const __half* __restrict__ W,
             const float* __restrict__ bias, const float* __restrict__ res,
             float* __restrict__ C, __half* __restrict__ Ch, int M, int N, int K)
{
    extern __shared__ uint32_t smh[];
    const uint32_t smb = smem_u32(smh);

    const int t = threadIdx.x;
    const int wid = t >> 5, lane = t & 31;
    const int gid = lane >> 2, tig = lane & 3;
    const int wm = wid >> 2;              // 0..1
    const int wn = wid & 3;               // 0..3
    const int bm = blockIdx.y * 128;
    const int bn = blockIdx.x * 128;

    const int ar = t >> 3;                // 0..31
    const int ac8 = (t & 7) * 8;
    const __half* Abase = A + (size_t)(bm + ar) * K + ac8;
    const __half* Wbase = W + (size_t)(bn + ar) * K + ac8;
    const uint32_t stoff = (uint32_t)(ar * ROWW + (t & 7) * 4) * 4u;

    const int a_r = lane & 15, a_k4 = (lane >> 4) * 4;
    uint32_t aOff[4];
#pragma unroll
    for (int i = 0; i < 4; i++)
        aOff[i] = (uint32_t)((wm * 64 + i * 16 + a_r) * ROWW + a_k4) * 4u;
    const int b_r = lane & 7, b_sel = (lane >> 4) & 1, b_k4 = ((lane >> 3) & 1) * 4;
    uint32_t bOff[2];
#pragma unroll
    for (int jj = 0; jj < 2; jj++)
        bOff[jj] = (uint32_t)((wn * 32 + (jj * 2 + b_sel) * 8 + b_r) * ROWW + b_k4) * 4u;

    float acc[4][4][4];
#pragma unroll
    for (int i = 0; i < 4; i++)
#pragma unroll
        for (int j = 0; j < 4; j++)
#pragma unroll
            for (int q = 0; q < 4; q++) acc[i][j][q] = 0.f;

    const int KT = K >> 6;

    // prologue: issue stages 0 and 1 as separate commit groups
#pragma unroll
    for (int s = 0; s < 2; s++) {
        const __half* Ap = Abase + (size_t)s * 64;
        const __half* Wp = Wbase + (size_t)s * 64;
        uint32_t adst = smb + (uint32_t)(s * TILE_W) * 4u + stoff;
        uint32_t bdst = smb + (uint32_t)((3 + s) * TILE_W) * 4u + stoff;
#pragma unroll
        for (int i = 0; i < 4; i++) {
            CP_ASYNC16(adst + (uint32_t)(i * 32 * ROWW * 4), Ap + (size_t)(i * 32) * K);
            CP_ASYNC16(bdst + (uint32_t)(i * 32 * ROWW * 4), Wp + (size_t)(i * 32) * K);
        }
        CP_COMMIT();
    }

    int stage = 0;
    for (int kt = 0; kt < KT; kt++) {
        CP_WAIT1();            // tile kt resident (kt+1 may still be in flight)
        __syncthreads();       // all warps done computing kt-1; smem for kt visible

        // issue loads for kt+2 into buffer (stage+2)%3 (last read at kt-1)
        if (kt + 2 < KT) {
            int s2 = stage + 2;
            if (s2 >= 3) s2 -= 3;
            const __half* Ap = Abase + (size_t)(kt + 2) * 64;
            const __half* Wp = Wbase + (size_t)(kt + 2) * 64;
            uint32_t adst = smb + (uint32_t)(s2 * TILE_W) * 4u + stoff;
            uint32_t bdst = smb + (uint32_t)((3 + s2) * TILE_W) * 4u + stoff;
#pragma unroll
            for (int i = 0; i < 4; i++) {
                CP_ASYNC16(adst + (uint32_t)(i * 32 * ROWW * 4), Ap + (size_t)(i * 32) * K);
                CP_ASYNC16(bdst + (uint32_t)(i * 32 * ROWW * 4), Wp + (size_t)(i * 32) * K);
            }
            CP_COMMIT();
        } else {
            CP_COMMIT();       // keep group count in lockstep for wait_group 1
        }

        const uint32_t aBase = smb + (uint32_t)(stage * TILE_W) * 4u;
        const uint32_t bBase = smb + (uint32_t)((3 + stage) * TILE_W) * 4u;
#pragma unroll
        for (int kk = 0; kk < 4; kk++) {
            uint32_t a[4][4], b[4][2];
#pragma unroll
            for (int i = 0; i < 4; i++)
                LDSM_X4(a[i][0], a[i][1], a[i][2], a[i][3],
                        aBase + aOff[i] + (uint32_t)(kk * 32));
#pragma unroll
            for (int jj = 0; jj < 2; jj++)
                LDSM_X4(b[jj*2][0], b[jj*2][1], b[jj*2+1][0], b[jj*2+1][1],
                        bBase + bOff[jj] + (uint32_t)(kk * 32));
#pragma unroll
            for (int i = 0; i < 4; i++)
#pragma unroll
                for (int j = 0; j < 4; j++)
                    mma16(acc[i][j], a[i], b[j]);
        }

        stage = (stage == 2) ? 0 : (stage + 1);
    }

    // epilogue
#pragma unroll
    for (int j = 0; j < 4; j++) {
        const int gc = bn + wn * 32 + j * 8 + 2 * tig;
        const float2 bia = *(const float2*)(bias + gc);
#pragma unroll
        for (int i = 0; i < 4; i++) {
            const int gr = bm + wm * 64 + i * 16 + gid;
            float2 v0, v1;
            v0.x = acc[i][j][0] + bia.x; v0.y = acc[i][j][1] + bia.y;
            v1.x = acc[i][j][2] + bia.x; v1.y = acc[i][j][3] + bia.y;
            if (res) {
                float2 r0 = *(const float2*)(res + (size_t)gr * N + gc);
                float2 r1 = *(const float2*)(res + (size_t)(gr + 8) * N + gc);
                v0.x += r0.x; v0.y += r0.y; v1.x += r1.x; v1.y += r1.y;
            }
            if (GELU) {
                v0.x = 0.5f * v0.x * (1.0f + erff(v0.x * 0.70710678118654752f));
                v0.y = 0.5f * v0.y * (1.0f + erff(v0.y * 0.70710678118654752f));
                v1.x = 0.5f * v1.x * (1.0f + erff(v1.x * 0.70710678118654752f));
                v1.y = 0.5f * v1.y * (1.0f + erff(v1.y * 0.70710678118654752f));
            }
            if (OMODE != 1) {
                *(float2*)(C + (size_t)gr * N + gc) = v0;
                *(float2*)(C + (size_t)(gr + 8) * N + gc) = v1;
            }
            if (OMODE >= 1) {
                *(__half2*)(Ch + (size_t)gr * N + gc) = __floats2half2_rn(v0.x, v0.y);
                *(__half2*)(Ch + (size_t)(gr + 8) * N + gc) = __floats2half2_rn(v1.x, v1.y);
            }
        }
    }
}

// ================= local windowed causal attention (R10; fp16 output) ========
#define LQS 68
#define LVS 132
#define PST 136
#define LA_SMEM_F (64*LQS + 128*LQS + 64*LVS + 32*PST)

__global__ __launch_bounds__(256, 2)
void local_attn_kernel(const float* __restrict__ qkv, __half* __restrict__ outh)
{
    extern __shared__ float sml[];
    float* Qs = sml;
    float* Ks = Qs + 64 * LQS;
    float* Vt = Ks + 128 * LQS;
    float* Pb = Vt + 64 * LVS;

    const int qt = blockIdx.x, h = blockIdx.y, b = blockIdx.z;
    const int t = threadIdx.x;
    const int q0 = qt * 64;
    const int kbase = q0 - 64;

    for (int idx = t; idx < 64 * 16; idx += 256) {
        int r = idx >> 4, c4 = (idx & 15) << 2;
        float4 v = *(const float4*)(qkv + ((size_t)(b*SEQ + q0 + r)) * (3*DM) + h*HD + c4);
        *(float4*)(Qs + r * LQS + c4) = v;
    }
    for (int idx = t; idx < 128 * 16; idx += 256) {
        int r = idx >> 4, c4 = (idx & 15) << 2;
        int j = kbase + r;
        if (j >= 0) {
            float4 kv = *(const float4*)(qkv + ((size_t)(b*SEQ + j)) * (3*DM) + DM + h*HD + c4);
            *(float4*)(Ks + r * LQS + c4) = kv;
        }
    }
#pragma unroll
    for (int pass = 0; pass < 8; pass++) {
        int r  = (t & 31) + 32 * (pass & 3);
        int c4 = (((t >> 5) + 8 * (pass >> 2))) << 2;
        int j = kbase + r;
        if (j >= 0) {
            float4 vv = *(const float4*)(qkv + ((size_t)(b*SEQ + j)) * (3*DM) + 2*DM + h*HD + c4);
            Vt[(c4+0) * LVS + r] = vv.x;
            Vt[(c4+1) * LVS + r] = vv.y;
            Vt[(c4+2) * LVS + r] = vv.z;
            Vt[(c4+3) * LVS + r] = vv.w;
        }
    }
    __syncthreads();

    const int warp = t >> 5, lane = t & 31;

    for (int g = 0; g < 2; g++) {
        const int iq0 = warp * 8 + g * 4;
        const int i0 = q0 + iq0;

        int rlo0 = max(0, i0 - WIN) - kbase;
        int rhi3 = (i0 + 3) - kbase;
        const int klo = rlo0;
        const int nk = rhi3 - klo + 1;

        float sc[4][3];
        float mx[4] = {-1e30f, -1e30f, -1e30f, -1e30f};

#pragma unroll
        for (int it = 0; it < 3; it++) {
            const int off = it * 32 + lane;
            const bool kvalid = off < nk;
            const int krow = klo + (kvalid ? off : 0);
            const float4* kr4 = (const float4*)(Ks + krow * LQS);
            float2 acc[4];
#pragma unroll
            for (int q = 0; q < 4; q++) acc[q] = make_float2(0.f, 0.f);
#pragma unroll
            for (int c = 0; c < 4; c++) {
                float4 k0 = kr4[c*4+0];
                float4 k1 = kr4[c*4+1];
                float4 k2 = kr4[c*4+2];
                float4 k3 = kr4[c*4+3];
#pragma unroll
                for (int q = 0; q < 4; q++) {
                    const float4* qr4 = (const float4*)(Qs + (iq0 + q) * LQS) + c*4;
                    float4 q0v = qr4[0], q1v = qr4[1], q2v = qr4[2], q3v = qr4[3];
                    acc[q].x = fmaf(q0v.x, k0.x, acc[q].x);
                    acc[q].y = fmaf(q0v.y, k0.y, acc[q].y);
                    acc[q].x = fmaf(q0v.z, k0.z, acc[q].x);
                    acc[q].y = fmaf(q0v.w, k0.w, acc[q].y);
                    acc[q].x = fmaf(q1v.x, k1.x, acc[q].x);
                    acc[q].y = fmaf(q1v.y, k1.y, acc[q].y);
                    acc[q].x = fmaf(q1v.z, k1.z, acc[q].x);
                    acc[q].y = fmaf(q1v.w, k1.w, acc[q].y);
                    acc[q].x = fmaf(q2v.x, k2.x, acc[q].x);
                    acc[q].y = fmaf(q2v.y, k2.y, acc[q].y);
                    acc[q].x = fmaf(q2v.z, k2.z, acc[q].x);
                    acc[q].y = fmaf(q2v.w, k2.w, acc[q].y);
                    acc[q].x = fmaf(q3v.x, k3.x, acc[q].x);
                    acc[q].y = fmaf(q3v.y, k3.y, acc[q].y);
                    acc[q].x = fmaf(q3v.z, k3.z, acc[q].x);
                    acc[q].y = fmaf(q3v.w, k3.w, acc[q].y);
                }
            }
            const int row = klo + off;
#pragma unroll
            for (int q = 0; q < 4; q++) {
                const int rlo_q = max(0, (i0 + q) - WIN) - kbase;
                const int rhi_q = (i0 + q) - kbase;
                float s = (acc[q].x + acc[q].y) * 0.125f;
                bool valid = kvalid && (row >= rlo_q) && (row <= rhi_q);
                s = valid ? s : -1e30f;
                sc[q][it] = s;
                mx[q] = fmaxf(mx[q], s);
            }
        }

        float inv_s[4];
#pragma unroll
        for (int q = 0; q < 4; q++) {
            float m = mx[q];
#pragma unroll
            for (int o = 16; o; o >>= 1) m = fmaxf(m, __shfl_xor_sync(0xffffffffu, m, o));
            float* pwq = Pb + (warp * 4 + q) * PST;
            float sum = 0.f;
#pragma unroll
            for (int it = 0; it < 3; it++) {
                const int off = it * 32 + lane;
                float e = expf(sc[q][it] - m);
                if (off < nk) pwq[klo + off] = e;
                sum += (off < nk) ? e : 0.f;
            }
#pragma unroll
            for (int o = 16; o; o >>= 1) sum += __shfl_xor_sync(0xffffffffu, sum, o);
            inv_s[q] = 1.0f / sum;
        }

        const int lo4 = klo & ~3;
        const int hi  = klo + nk;
        const int hi4 = (hi + 3) & ~3;
#pragma unroll
        for (int q = 0; q < 4; q++) {
            float* pwq = Pb + (warp * 4 + q) * PST;
            if (lane < klo - lo4) pwq[lo4 + lane] = 0.f;
            if (lane < hi4 - hi)  pwq[hi + lane] = 0.f;
        }
        __syncwarp();

        float4 a0[4], a1[4];
#pragma unroll
        for (int q = 0; q < 4; q++) {
            a0[q] = make_float4(0.f, 0.f, 0.f, 0.f);
            a1[q] = make_float4(0.f, 0.f, 0.f, 0.f);
        }
        const float* va = Vt + lane * LVS;
        const float* vb = Vt + (lane + 32) * LVS;
        for (int r4 = lo4; r4 < hi4; r4 += 4) {
            float4 x4 = *(const float4*)(va + r4);
            float4 y4 = *(const float4*)(vb + r4);
#pragma unroll
            for (int q = 0; q < 4; q++) {
                float4 p = *(const float4*)(Pb + (warp * 4 + q) * PST + r4);
                a0[q].x = fmaf(p.x, x4.x, a0[q].x);
                a0[q].y = fmaf(p.y, x4.y, a0[q].y);
                a0[q].z = fmaf(p.z, x4.z, a0[q].z);
                a0[q].w = fmaf(p.w, x4.w, a0[q].w);
                a1[q].x = fmaf(p.x, y4.x, a1[q].x);
                a1[q].y = fmaf(p.y, y4.y, a1[q].y);
                a1[q].z = fmaf(p.z, y4.z, a1[q].z);
                a1[q].w = fmaf(p.w, y4.w, a1[q].w);
            }
        }
#pragma unroll
        for (int q = 0; q < 4; q++) {
            __half* dst = outh + ((size_t)(b*SEQ + i0 + q)) * DM + h*HD;
            dst[lane]      = __float2half_rn(((a0[q].x + a0[q].y) + (a0[q].z + a0[q].w)) * inv_s[q]);
            dst[lane + 32] = __float2half_rn(((a1[q].x + a1[q].y) + (a1[q].z + a1[q].w)) * inv_s[q]);
        }
        __syncwarp();
    }
}

// ---------------- global attention vs 32 anchors (fp16 output) --------------
#define GQS 68
#define GVS 36
__global__ __launch_bounds__(256)
void global_attn_kernel(const float* __restrict__ q, const float* __restrict__ kv,
                        __half* __restrict__ outh)
{
    __shared__ __align__(16) float Qs[64 * GQS];
    __shared__ __align__(16) float Ks[32 * GQS];
    __shared__ __align__(16) float Vt[64 * GVS];
    __shared__ __align__(16) float Pb[8][GVS];

    const int qt = blockIdx.x, h = blockIdx.y, b = blockIdx.z;
    const int t = threadIdx.x;
    const int q0 = qt * 64;

    for (int idx = t; idx < 64 * 16; idx += 256) {
        int r = idx >> 4, c4 = (idx & 15) << 2;
        float4 v = *(const float4*)(q + ((size_t)(b*SEQ + q0 + r)) * DM + h*HD + c4);
        *(float4*)(Qs + r * GQS + c4) = v;
    }
    for (int idx = t; idx < 32 * 16; idx += 256) {
        int r = idx >> 4, c4 = (idx & 15) << 2;
        float4 kk = *(const float4*)(kv + ((size_t)(b*NA + r)) * (2*DM) + h*HD + c4);
        *(float4*)(Ks + r * GQS + c4) = kk;
    }
#pragma unroll
    for (int pass = 0; pass < 2; pass++) {
        int r  = t & 31;
        int c4 = (((t >> 5) + 8 * pass)) << 2;
        float4 vv = *(const float4*)(kv + ((size_t)(b*NA + r)) * (2*DM) + DM + h*HD + c4);
        Vt[(c4+0) * GVS + r] = vv.x;
        Vt[(c4+1) * GVS + r] = vv.y;
        Vt[(c4+2) * GVS + r] = vv.z;
        Vt[(c4+3) * GVS + r] = vv.w;
    }
    __syncthreads();

    const int warp = t >> 5, lane = t & 31;
    for (int iq = warp * 8; iq < warp * 8 + 8; iq++) {
        const float4* qr4 = (const float4*)(Qs + iq * GQS);
        const float4* kr4 = (const float4*)(Ks + lane * GQS);
        float s = 0.f;
#pragma unroll
        for (int d = 0; d < 16; d++) {
            float4 q4 = qr4[d], k4 = kr4[d];
            s += q4.x*k4.x + q4.y*k4.y + q4.z*k4.z + q4.w*k4.w;
        }
        s *= 0.125f;
        float smax = s;
#pragma unroll
        for (int o = 16; o; o >>= 1) smax = fmaxf(smax, __shfl_xor_sync(0xffffffffu, smax, o));
        float e = expf(s - smax);
        float ssum = e;
#pragma unroll
        for (int o = 16; o; o >>= 1) ssum += __shfl_xor_sync(0xffffffffu, ssum, o);
        Pb[warp][lane] = e;
        __syncwarp();

        float o0 = 0.f, o1 = 0.f;
        const float* va = Vt + lane * GVS;
        const float* vb = Vt + (lane + 32) * GVS;
#pragma unroll
        for (int j4 = 0; j4 < 32; j4 += 4) {
            float4 p  = *(const float4*)(&Pb[warp][j4]);
            float4 a4 = *(const float4*)(va + j4);
            float4 b4 = *(const float4*)(vb + j4);
            o0 += p.x*a4.x + p.y*a4.y + p.z*a4.z + p.w*a4.w;
            o1 += p.x*b4.x + p.y*b4.y + p.z*b4.z + p.w*b4.w;
        }
        const float inv = 1.0f / ssum;
        __half* dst = outh + ((size_t)(b*SEQ + q0 + iq)) * DM + h*HD;
        dst[lane]      = __float2half_rn(o0 * inv);
        dst[lane + 32] = __float2half_rn(o1 * inv);
        __syncwarp();
    }
}

// ---------------- layernorm (optional fp16 copy) ----------------
__global__ __launch_bounds__(128)
void ln_kernel(const float* __restrict__ x, const float* __restrict__ g,
               const float* __restrict__ be, float* __restrict__ out,
               __half* __restrict__ outh)
{
    __shared__ float red[8];
    const int row = blockIdx.x;
    const int t = threadIdx.x;
    float4 v = ((const float4*)(x + (size_t)row * DM))[t];
    float s  = v.x + v.y + v.z + v.w;
    float ss = v.x*v.x + v.y*v.y + v.z*v.z + v.w*v.w;
#pragma unroll
    for (int o = 16; o; o >>= 1) {
        s  += __shfl_xor_sync(0xffffffffu, s, o);
        ss += __shfl_xor_sync(0xffffffffu, ss, o);
    }
    const int warp = t >> 5, lane = t & 31;
    if (lane == 0) { red[warp] = s; red[warp + 4] = ss; }
    __syncthreads();
    if (t == 0) {
        red[0] = red[0] + red[1] + red[2] + red[3];
        red[4] = red[4] + red[5] + red[6] + red[7];
    }
    __syncthreads();
    float mu  = red[0] * (1.0f / DM);
    float var = red[4] * (1.0f / DM) - mu * mu;
    float inv = rsqrtf(var + 1e-5f);
    float4 gg = ((const float4*)g)[t];
    float4 bb = ((const float4*)be)[t];
    float4 o;
    o.x = (v.x - mu) * inv * gg.x + bb.x;
    o.y = (v.y - mu) * inv * gg.y + bb.y;
    o.z = (v.z - mu) * inv * gg.z + bb.z;
    o.w = (v.w - mu) * inv * gg.w + bb.w;
    ((float4*)(out + (size_t)row * DM))[t] = o;
    if (outh) {
        __half2* dh = (__half2*)(outh + (size_t)row * DM) + t * 2;
        dh[0] = __floats2half2_rn(o.x, o.y);
        dh[1] = __floats2half2_rn(o.z, o.w);
    }
}

// ---------------- launch ----------------
extern "C" void kernel_launch(void* const* d_in, const int* in_sizes, int n_in,
                              void* d_out, int out_size)
{
    const float* x      = (const float*)d_in[0];
    const float* anchors= (const float*)d_in[1];
    const float* lw_in  = (const float*)d_in[2];
    const float* lb_in  = (const float*)d_in[3];
    const float* lw_out = (const float*)d_in[4];
    const float* lb_out = (const float*)d_in[5];
    const float* gw_in  = (const float*)d_in[6];
    const float* gb_in  = (const float*)d_in[7];
    const float* gw_out = (const float*)d_in[8];
    const float* gb_out = (const float*)d_in[9];
    const float* w1     = (const float*)d_in[10];
    const float* b1     = (const float*)d_in[11];
    const float* w2     = (const float*)d_in[12];
    const float* b2     = (const float*)d_in[13];
    const float* g1     = (const float*)d_in[14];
    const float* be1    = (const float*)d_in[15];
    const float* g2     = (const float*)d_in[16];
    const float* be2    = (const float*)d_in[17];
    float* out = (float*)d_out;

    float *qkv, *x1, *q2, *kv2, *x2, *x3;
    __half *wth, *xh, *anchh, *attnh, *x1h, *x3h, *hh;
    cudaGetSymbolAddress((void**)&qkv,  g_qkv);
    cudaGetSymbolAddress((void**)&x1,   g_x1);
    cudaGetSymbolAddress((void**)&q2,   g_q2);
    cudaGetSymbolAddress((void**)&kv2,  g_kv2);
    cudaGetSymbolAddress((void**)&x2,   g_x2);
    cudaGetSymbolAddress((void**)&x3,   g_x3);
    cudaGetSymbolAddress((void**)&wth,  g_wth);
    cudaGetSymbolAddress((void**)&xh,   g_xh);
    cudaGetSymbolAddress((void**)&anchh,g_anchh);
    cudaGetSymbolAddress((void**)&attnh,g_attnh);
    cudaGetSymbolAddress((void**)&x1h,  g_x1h);
    cudaGetSymbolAddress((void**)&x3h,  g_x3h);
    cudaGetSymbolAddress((void**)&hh,   g_hh);

    const int smem_local = LA_SMEM_F * (int)sizeof(float);
    const int gemm_smem  = GEMM_SMEM_W * (int)sizeof(uint32_t);
    cudaFuncSetAttribute(local_attn_kernel, cudaFuncAttributeMaxDynamicSharedMemorySize, smem_local);
    cudaFuncSetAttribute((const void*)gemm_hh<false,0>, cudaFuncAttributeMaxDynamicSharedMemorySize, gemm_smem);
    cudaFuncSetAttribute((const void*)gemm_hh<false,2>, cudaFuncAttributeMaxDynamicSharedMemorySize, gemm_smem);
    cudaFuncSetAttribute((const void*)gemm_hh<true,1>,  cudaFuncAttributeMaxDynamicSharedMemorySize, gemm_smem);

    dim3 thr(256);

    // [1] weights + anchors -> fp16
    cvt_all<<<(WTF_TOTAL + ANCH_N + 255) / 256, 256>>>(
        lw_in, lw_out, gw_in, gw_out, w1, w2, anchors, wth, anchh);
    // [2] x -> fp16
    cvt4<<<((MROWS * DM / 4) + 255) / 256, 256>>>(x, xh, MROWS * DM / 4);
    // [3] anchor k,v projection (f32 out)
    gemm_hh<false,0><<<dim3(1024/128, MAROWS/128), thr, gemm_smem>>>(
        anchh, wth + OFF_GWIN + 512*512, gb_in + 512, nullptr, kv2, nullptr, MAROWS, 2*DM, DM);
    // [4] local QKV projection (f32 out)   <-- ncu capture target
    gemm_hh<false,0><<<dim3(1536/128, MROWS/128), thr, gemm_smem>>>(
        xh, wth + OFF_LWIN, lb_in, nullptr, qkv, nullptr, MROWS, 3*DM, DM);
    // [5] windowed causal attention -> fp16
    local_attn_kernel<<<dim3(SEQ/64, NH, BATCH), thr, smem_local>>>(qkv, attnh);
    // [6] local out-proj + residual(x) -> x1 (f32) + x1h (f16)
    gemm_hh<false,2><<<dim3(DM/128, MROWS/128), thr, gemm_smem>>>(
        attnh, wth + OFF_LWOUT, lb_out, x, x1, x1h, MROWS, DM, DM);
    // [7] global q projection of x1h (f32 out)
    gemm_hh<false,0><<<dim3(DM/128, MROWS/128), thr, gemm_smem>>>(
        x1h, wth + OFF_GWIN, gb_in, nullptr, q2, nullptr, MROWS, DM, DM);
    // [8] global attention -> fp16
    global_attn_kernel<<<dim3(SEQ/64, NH, BATCH), thr>>>(q2, kv2, attnh);
    // [9] global out-proj + residual(x1) -> x2 (f32)
    gemm_hh<false,0><<<dim3(DM/128, MROWS/128), thr, gemm_smem>>>(
        attnh, wth + OFF_GWOUT, gb_out, x1, x2, nullptr, MROWS, DM, DM);
    // [10] LN1 -> x3 (f32) + x3h (f16)
    ln_kernel<<<MROWS, 128>>>(x2, g1, be1, x3, x3h);
    // [11] FFN1 + exact GELU -> hh (f16 only)
    gemm_hh<true,1><<<dim3(FF/128, MROWS/128), thr, gemm_smem>>>(
        x3h, wth + OFF_W1, b1, nullptr, nullptr, hh, MROWS, FF, DM);
    // [12] FFN2 + residual(x3) -> x2 (f32)
    gemm_hh<false,0><<<dim3(DM/128, MROWS/128), thr, gemm_smem>>>(
        hh, wth + OFF_W2, b2, x3, x2, nullptr, MROWS, DM, FF);
    // [13] LN2 -> out
    ln_kernel<<<MROWS, 128>>>(x2, g2, be2, out, nullptr);
}

// round 15
// speedup vs baseline: 1.1782x; 1.1782x over previous
#include <cuda_runtime.h>
#include <cuda_fp16.h>
#include <math.h>
#include <stdint.h>

#define BATCH 64
#define SEQ   512
#define DM    512
#define NH    8
#define HD    64
#define WIN   64
#define NA    32
#define FF    2048
#define MROWS (BATCH*SEQ)     // 32768
#define MAROWS (BATCH*NA)     // 2048

// ---------------- scratch ----------------
__device__ float g_x1 [(size_t)MROWS * DM];
__device__ float g_q2 [(size_t)MROWS * DM];
__device__ float g_kv2[(size_t)MAROWS * 2 * DM];
__device__ float g_x2 [(size_t)MROWS * DM];
__device__ float g_x3 [(size_t)MROWS * DM];
// fp16 buffers
__device__ __half g_qkvh [(size_t)MROWS * 3 * DM];
__device__ __half g_xh   [(size_t)MROWS * DM];
__device__ __half g_anchh[(size_t)MAROWS * DM];
__device__ __half g_attnh[(size_t)MROWS * DM];
__device__ __half g_x1h  [(size_t)MROWS * DM];
__device__ __half g_x3h  [(size_t)MROWS * DM];
__device__ __half g_hh   [(size_t)MROWS * FF];
// fp16 weights, packed
#define SZ_LWIN  786432
#define SZ_LWOUT 262144
#define SZ_GWIN  786432
#define SZ_GWOUT 262144
#define SZ_W1    1048576
#define SZ_W2    1048576
#define OFF_LWIN  0
#define OFF_LWOUT (OFF_LWIN + SZ_LWIN)
#define OFF_GWIN  (OFF_LWOUT + SZ_LWOUT)
#define OFF_GWOUT (OFF_GWIN + SZ_GWIN)
#define OFF_W1    (OFF_GWOUT + SZ_GWOUT)
#define OFF_W2    (OFF_W1 + SZ_W1)
#define WTF_TOTAL (OFF_W2 + SZ_W2)
#define ANCH_N    (MAROWS * DM)
__device__ __half g_wth[(size_t)WTF_TOTAL];

// ================= helpers =================
__device__ __forceinline__ uint32_t smem_u32(const void* p) {
    uint32_t a;
    asm("{ .reg .u64 t; cvta.to.shared.u64 t, %1; cvt.u32.u64 %0, t; }" : "=r"(a) : "l"(p));
    return a;
}
__device__ __forceinline__ void mma16(float* c, const uint32_t* a, const uint32_t* b) {
    asm volatile(
        "mma.sync.aligned.m16n8k16.row.col.f32.f16.f16.f32 "
        "{%0,%1,%2,%3}, {%4,%5,%6,%7}, {%8,%9}, {%0,%1,%2,%3};"
        : "+f"(c[0]), "+f"(c[1]), "+f"(c[2]), "+f"(c[3])
        : "r"(a[0]), "r"(a[1]), "r"(a[2]), "r"(a[3]),
          "r"(b[0]), "r"(b[1]));
}
#define LDSM_X4(r0, r1, r2, r3, addr) \
    asm volatile("ldmatrix.sync.aligned.m8n8.x4.shared.b16 {%0,%1,%2,%3}, [%4];" \
        : "=r"(r0), "=r"(r1), "=r"(r2), "=r"(r3) : "r"(addr))
#define CP_ASYNC16(dst, src) \
    asm volatile("cp.async.cg.shared.global [%0], [%1], 16;" :: "r"(dst), "l"(src) : "memory")
#define CP_COMMIT() asm volatile("cp.async.commit_group;" ::: "memory")
#define CP_WAIT1()  asm volatile("cp.async.wait_group 1;" ::: "memory")

// ---------------- weight + anchor fp16 pre-convert (one launch) --------
__global__ __launch_bounds__(256)
void cvt_all(const float* __restrict__ lw_in, const float* __restrict__ lw_out,
             const float* __restrict__ gw_in, const float* __restrict__ gw_out,
             const float* __restrict__ w1, const float* __restrict__ w2,
             const float* __restrict__ anch,
             __half* __restrict__ dst, __half* __restrict__ anch_h)
{
    int i = blockIdx.x * 256 + threadIdx.x;
    if (i >= WTF_TOTAL + ANCH_N) return;
    if (i >= WTF_TOTAL) {
        anch_h[i - WTF_TOTAL] = __float2half_rn(anch[i - WTF_TOTAL]);
        return;
    }
    const float* src;
    int local;
    if      (i < OFF_LWOUT) { src = lw_in;  local = i - OFF_LWIN; }
    else if (i < OFF_GWIN)  { src = lw_out; local = i - OFF_LWOUT; }
    else if (i < OFF_GWOUT) { src = gw_in;  local = i - OFF_GWIN; }
    else if (i < OFF_W1)    { src = gw_out; local = i - OFF_GWOUT; }
    else if (i < OFF_W2)    { src = w1;     local = i - OFF_W1; }
    else                    { src = w2;     local = i - OFF_W2; }
    dst[i] = __float2half_rn(src[local]);
}

// ---------------- vectorized f32 -> f16 (for x) ----------------
__global__ __launch_bounds__(256)
void cvt4(const float* __restrict__ src, __half* __restrict__ dst, int n4)
{
    int i = blockIdx.x * 256 + threadIdx.x;
    if (i < n4) {
        float4 v = ((const float4*)src)[i];
        ((__half2*)dst)[i * 2]     = __floats2half2_rn(v.x, v.y);
        ((__half2*)dst)[i * 2 + 1] = __floats2half2_rn(v.z, v.w);
    }
}

// ================= fp16 GEMM: 3-stage cp.async pipeline (R14, passing) ======
#define ROWW 36
#define TILE_W (128 * ROWW)
#define GEMM_SMEM_W (6 * TILE_W)

template<bool GELU, int OMODE>
__global__ __launch_bounds__(256, 2)
void gemm_hh(const __half* __restrict__ A, const __half* __restrict__ W,
             const float* __restrict__ bias, const float* __restrict__ res,
             float* __restrict__ C, __half* __restrict__ Ch, int M, int N, int K)
{
    extern __shared__ uint32_t smh[];
    const uint32_t smb = smem_u32(smh);

    const int t = threadIdx.x;
    const int wid = t >> 5, lane = t & 31;
    const int gid = lane >> 2, tig = lane & 3;
    const int wm = wid >> 2;
    const int wn = wid & 3;
    const int bm = blockIdx.y * 128;
    const int bn = blockIdx.x * 128;

    const int ar = t >> 3;
    const int ac8 = (t & 7) * 8;
    const __half* Abase = A + (size_t)(bm + ar) * K + ac8;
    const __half* Wbase = W + (size_t)(bn + ar) * K + ac8;
    const uint32_t stoff = (uint32_t)(ar * ROWW + (t & 7) * 4) * 4u;

    const int a_r = lane & 15, a_k4 = (lane >> 4) * 4;
    uint32_t aOff[4];
#pragma unroll
    for (int i = 0; i < 4; i++)
        aOff[i] = (uint32_t)((wm * 64 + i * 16 + a_r) * ROWW + a_k4) * 4u;
    const int b_r = lane & 7, b_sel = (lane >> 4) & 1, b_k4 = ((lane >> 3) & 1) * 4;
    uint32_t bOff[2];
#pragma unroll
    for (int jj = 0; jj < 2; jj++)
        bOff[jj] = (uint32_t)((wn * 32 + (jj * 2 + b_sel) * 8 + b_r) * ROWW + b_k4) * 4u;

    float acc[4][4][4];
#pragma unroll
    for (int i = 0; i < 4; i++)
#pragma unroll
        for (int j = 0; j < 4; j++)
#pragma unroll
            for (int q = 0; q < 4; q++) acc[i][j][q] = 0.f;

    const int KT = K >> 6;

#pragma unroll
    for (int s = 0; s < 2; s++) {
        const __half* Ap = Abase + (size_t)s * 64;
        const __half* Wp = Wbase + (size_t)s * 64;
        uint32_t adst = smb + (uint32_t)(s * TILE_W) * 4u + stoff;
        uint32_t bdst = smb + (uint32_t)((3 + s) * TILE_W) * 4u + stoff;
#pragma unroll
        for (int i = 0; i < 4; i++) {
            CP_ASYNC16(adst + (uint32_t)(i * 32 * ROWW * 4), Ap + (size_t)(i * 32) * K);
            CP_ASYNC16(bdst + (uint32_t)(i * 32 * ROWW * 4), Wp + (size_t)(i * 32) * K);
        }
        CP_COMMIT();
    }

    int stage = 0;
    for (int kt = 0; kt < KT; kt++) {
        CP_WAIT1();
        __syncthreads();

        if (kt + 2 < KT) {
            int s2 = stage + 2;
            if (s2 >= 3) s2 -= 3;
            const __half* Ap = Abase + (size_t)(kt + 2) * 64;
            const __half* Wp = Wbase + (size_t)(kt + 2) * 64;
            uint32_t adst = smb + (uint32_t)(s2 * TILE_W) * 4u + stoff;
            uint32_t bdst = smb + (uint32_t)((3 + s2) * TILE_W) * 4u + stoff;
#pragma unroll
            for (int i = 0; i < 4; i++) {
                CP_ASYNC16(adst + (uint32_t)(i * 32 * ROWW * 4), Ap + (size_t)(i * 32) * K);
                CP_ASYNC16(bdst + (uint32_t)(i * 32 * ROWW * 4), Wp + (size_t)(i * 32) * K);
            }
            CP_COMMIT();
        } else {
            CP_COMMIT();
        }

        const uint32_t aBase = smb + (uint32_t)(stage * TILE_W) * 4u;
        const uint32_t bBase = smb + (uint32_t)((3 + stage) * TILE_W) * 4u;
#pragma unroll
        for (int kk = 0; kk < 4; kk++) {
            uint32_t a[4][4], b[4][2];
#pragma unroll
            for (int i = 0; i < 4; i++)
                LDSM_X4(a[i][0], a[i][1], a[i][2], a[i][3],
                        aBase + aOff[i] + (uint32_t)(kk * 32));
#pragma unroll
            for (int jj = 0; jj < 2; jj++)
                LDSM_X4(b[jj*2][0], b[jj*2][1], b[jj*2+1][0], b[jj*2+1][1],
                        bBase + bOff[jj] + (uint32_t)(kk * 32));
#pragma unroll
            for (int i = 0; i < 4; i++)
#pragma unroll
                for (int j = 0; j < 4; j++)
                    mma16(acc[i][j], a[i], b[j]);
        }

        stage = (stage == 2) ? 0 : (stage + 1);
    }

#pragma unroll
    for (int j = 0; j < 4; j++) {
        const int gc = bn + wn * 32 + j * 8 + 2 * tig;
        const float2 bia = *(const float2*)(bias + gc);
#pragma unroll
        for (int i = 0; i < 4; i++) {
            const int gr = bm + wm * 64 + i * 16 + gid;
            float2 v0, v1;
            v0.x = acc[i][j][0] + bia.x; v0.y = acc[i][j][1] + bia.y;
            v1.x = acc[i][j][2] + bia.x; v1.y = acc[i][j][3] + bia.y;
            if (res) {
                float2 r0 = *(const float2*)(res + (size_t)gr * N + gc);
                float2 r1 = *(const float2*)(res + (size_t)(gr + 8) * N + gc);
                v0.x += r0.x; v0.y += r0.y; v1.x += r1.x; v1.y += r1.y;
            }
            if (GELU) {
                v0.x = 0.5f * v0.x * (1.0f + erff(v0.x * 0.70710678118654752f));
                v0.y = 0.5f * v0.y * (1.0f + erff(v0.y * 0.70710678118654752f));
                v1.x = 0.5f * v1.x * (1.0f + erff(v1.x * 0.70710678118654752f));
                v1.y = 0.5f * v1.y * (1.0f + erff(v1.y * 0.70710678118654752f));
            }
            if (OMODE != 1) {
                *(float2*)(C + (size_t)gr * N + gc) = v0;
                *(float2*)(C + (size_t)(gr + 8) * N + gc) = v1;
            }
            if (OMODE >= 1) {
                *(__half2*)(Ch + (size_t)gr * N + gc) = __floats2half2_rn(v0.x, v0.y);
                *(__half2*)(Ch + (size_t)(gr + 8) * N + gc) = __floats2half2_rn(v1.x, v1.y);
            }
        }
    }
}

// ================= local windowed causal attention — tensor core fp16 ========
// Per block (qt,h,b): 128 threads = 4 warps; warp w owns query rows w*16..w*16+15.
// S = Q@K^T (M=64,N=128,K=64), band mask, softmax, P fp16 -> smem, O = P@V (K=128).
// Fragment scheme identical to the validated GEMM (LDSM strides 36 / 68 words).
#define AQS 36    // words per Q/K row (72 halves, 64 used)
#define AVS 68    // words per Vt/P row (136 halves, 128 used)
#define LAH_SMEM_W (64*AQS + 128*AQS + 64*AVS + 64*AVS)   // 15616 words = 62464 B

__global__ __launch_bounds__(128, 3)
void local_attn_h(const __half* __restrict__ qkvh, __half* __restrict__ outh)
{
    extern __shared__ uint32_t smw[];
    __half* Qh = (__half*)smw;                  // [64][72] halves
    __half* Kh = Qh + 64 * (AQS * 2);           // [128][72]
    __half* Vh = Kh + 128 * (AQS * 2);          // [64][136] dim-major
    __half* Ph = Vh + 64 * (AVS * 2);           // [64][136]
    const uint32_t smb = smem_u32(smw);
    const uint32_t qBase = smb;
    const uint32_t kBase = smb + 64u * AQS * 4u;
    const uint32_t vBase = kBase + 128u * AQS * 4u;
    const uint32_t pBase = vBase + 64u * AVS * 4u;

    const int qt = blockIdx.x, h = blockIdx.y, b = blockIdx.z;
    const int t = threadIdx.x;
    const int w = t >> 5, lane = t & 31;
    const int gid = lane >> 2, tig = lane & 3;
    const int q0 = qt * 64;
    const int kbase = q0 - 64;

    // load Q (64 rows x 64 halves)
    for (int idx = t; idx < 64 * 8; idx += 128) {
        int r = idx >> 3, c8 = (idx & 7) * 8;
        float4 v = *(const float4*)(qkvh + ((size_t)(b*SEQ + q0 + r)) * (3*DM) + h*HD + c8);
        *(float4*)(Qh + r * 72 + c8) = v;
    }
    // load K (128 rows; j<0 rows left as garbage -> masked by boolean select)
    for (int idx = t; idx < 128 * 8; idx += 128) {
        int r = idx >> 3, c8 = (idx & 7) * 8;
        int j = kbase + r;
        if (j >= 0) {
            float4 v = *(const float4*)(qkvh + ((size_t)(b*SEQ + j)) * (3*DM) + DM + h*HD + c8);
            *(float4*)(Kh + r * 72 + c8) = v;
        }
    }
    // load V transposed (dim-major); zero for j<0 so P*V can't see garbage
    for (int idx = t; idx < 128 * 8; idx += 128) {
        int r = idx >> 3, c8 = (idx & 7) * 8;   // r = key row, c8 = dim chunk
        int j = kbase + r;
        __half vals[8];
        if (j >= 0) {
            *(float4*)vals = *(const float4*)(qkvh + ((size_t)(b*SEQ + j)) * (3*DM) + 2*DM + h*HD + c8);
        } else {
#pragma unroll
            for (int d = 0; d < 8; d++) vals[d] = __float2half_rn(0.f);
        }
#pragma unroll
        for (int d = 0; d < 8; d++) Vh[(c8 + d) * 136 + r] = vals[d];
    }
    __syncthreads();

    // ---- S = Q @ K^T ----
    const int b_r = lane & 7, b_sel = (lane >> 4) & 1, b_k4 = ((lane >> 3) & 1) * 4;
    const uint32_t aOffQ = (uint32_t)((w * 16 + (lane & 15)) * AQS + (lane >> 4) * 4) * 4u;

    float sacc[16][4];
#pragma unroll
    for (int nt = 0; nt < 16; nt++)
#pragma unroll
        for (int q = 0; q < 4; q++) sacc[nt][q] = 0.f;

#pragma unroll
    for (int kk = 0; kk < 4; kk++) {
        uint32_t a[4];
        LDSM_X4(a[0], a[1], a[2], a[3], qBase + aOffQ + (uint32_t)(kk * 32));
#pragma unroll
        for (int jj = 0; jj < 8; jj++) {
            uint32_t bf[4];
            uint32_t baddr = kBase +
                (uint32_t)(((jj * 2 + b_sel) * 8 + b_r) * AQS + b_k4) * 4u + (uint32_t)(kk * 32);
            LDSM_X4(bf[0], bf[1], bf[2], bf[3], baddr);
            mma16(sacc[jj*2],     a, bf);
            mma16(sacc[jj*2 + 1], a, bf + 2);
        }
    }

    // ---- mask + softmax ----
    const int r0 = w * 16 + gid, r1 = r0 + 8;   // local query rows
    float mx0 = -1e30f, mx1 = -1e30f;
#pragma unroll
    for (int nt = 0; nt < 16; nt++) {
        const int c0 = nt * 8 + 2 * tig, c1 = c0 + 1;
        bool ok00 = (c0 >= r0) && (c0 <= r0 + 64) && (kbase + c0 >= 0);
        bool ok01 = (c1 >= r0) && (c1 <= r0 + 64) && (kbase + c1 >= 0);
        bool ok10 = (c0 >= r1) && (c0 <= r1 + 64) && (kbase + c0 >= 0);
        bool ok11 = (c1 >= r1) && (c1 <= r1 + 64) && (kbase + c1 >= 0);
        sacc[nt][0] = ok00 ? sacc[nt][0] * 0.125f : -1e30f;
        sacc[nt][1] = ok01 ? sacc[nt][1] * 0.125f : -1e30f;
        sacc[nt][2] = ok10 ? sacc[nt][2] * 0.125f : -1e30f;
        sacc[nt][3] = ok11 ? sacc[nt][3] * 0.125f : -1e30f;
        mx0 = fmaxf(mx0, fmaxf(sacc[nt][0], sacc[nt][1]));
        mx1 = fmaxf(mx1, fmaxf(sacc[nt][2], sacc[nt][3]));
    }
#pragma unroll
    for (int o = 1; o <= 2; o <<= 1) {
        mx0 = fmaxf(mx0, __shfl_xor_sync(0xffffffffu, mx0, o));
        mx1 = fmaxf(mx1, __shfl_xor_sync(0xffffffffu, mx1, o));
    }
    float sum0 = 0.f, sum1 = 0.f;
#pragma unroll
    for (int nt = 0; nt < 16; nt++) {
        float e00 = expf(sacc[nt][0] - mx0);
        float e01 = expf(sacc[nt][1] - mx0);
        float e10 = expf(sacc[nt][2] - mx1);
        float e11 = expf(sacc[nt][3] - mx1);
        sum0 += e00 + e01;
        sum1 += e10 + e11;
        *(__half2*)(Ph + r0 * 136 + nt * 8 + 2 * tig) = __floats2half2_rn(e00, e01);
        *(__half2*)(Ph + r1 * 136 + nt * 8 + 2 * tig) = __floats2half2_rn(e10, e11);
    }
#pragma unroll
    for (int o = 1; o <= 2; o <<= 1) {
        sum0 += __shfl_xor_sync(0xffffffffu, sum0, o);
        sum1 += __shfl_xor_sync(0xffffffffu, sum1, o);
    }
    const float inv0 = 1.0f / sum0, inv1 = 1.0f / sum1;
    __syncwarp();

    // ---- O = P @ V ----
    const uint32_t aOffP = (uint32_t)((w * 16 + (lane & 15)) * AVS + (lane >> 4) * 4) * 4u;
    float oacc[8][4];
#pragma unroll
    for (int nt = 0; nt < 8; nt++)
#pragma unroll
        for (int q = 0; q < 4; q++) oacc[nt][q] = 0.f;

#pragma unroll
    for (int kk = 0; kk < 8; kk++) {
        uint32_t a[4];
        LDSM_X4(a[0], a[1], a[2], a[3], pBase + aOffP + (uint32_t)(kk * 32));
#pragma unroll
        for (int jj = 0; jj < 4; jj++) {
            uint32_t bf[4];
            uint32_t baddr = vBase +
                (uint32_t)(((jj * 2 + b_sel) * 8 + b_r) * AVS + b_k4) * 4u + (uint32_t)(kk * 32);
            LDSM_X4(bf[0], bf[1], bf[2], bf[3], baddr);
            mma16(oacc[jj*2],     a, bf);
            mma16(oacc[jj*2 + 1], a, bf + 2);
        }
    }

    // output (fp16)
#pragma unroll
    for (int nt = 0; nt < 8; nt++) {
        const int gc = h * HD + nt * 8 + 2 * tig;
        *(__half2*)(outh + (size_t)(b*SEQ + q0 + r0) * DM + gc) =
            __floats2half2_rn(oacc[nt][0] * inv0, oacc[nt][1] * inv0);
        *(__half2*)(outh + (size_t)(b*SEQ + q0 + r1) * DM + gc) =
            __floats2half2_rn(oacc[nt][2] * inv1, oacc[nt][3] * inv1);
    }
}

// ---------------- global attention vs 32 anchors (fp16 output; unchanged) ----
#define GQS 68
#define GVS 36
__global__ __launch_bounds__(256)
void global_attn_kernel(const float* __restrict__ q, const float* __restrict__ kv,
                        __half* __restrict__ outh)
{
    __shared__ __align__(16) float Qs[64 * GQS];
    __shared__ __align__(16) float Ks[32 * GQS];
    __shared__ __align__(16) float Vt[64 * GVS];
    __shared__ __align__(16) float Pb[8][GVS];

    const int qt = blockIdx.x, h = blockIdx.y, b = blockIdx.z;
    const int t = threadIdx.x;
    const int q0 = qt * 64;

    for (int idx = t; idx < 64 * 16; idx += 256) {
        int r = idx >> 4, c4 = (idx & 15) << 2;
        float4 v = *(const float4*)(q + ((size_t)(b*SEQ + q0 + r)) * DM + h*HD + c4);
        *(float4*)(Qs + r * GQS + c4) = v;
    }
    for (int idx = t; idx < 32 * 16; idx += 256) {
        int r = idx >> 4, c4 = (idx & 15) << 2;
        float4 kk = *(const float4*)(kv + ((size_t)(b*NA + r)) * (2*DM) + h*HD + c4);
        *(float4*)(Ks + r * GQS + c4) = kk;
    }
#pragma unroll
    for (int pass = 0; pass < 2; pass++) {
        int r  = t & 31;
        int c4 = (((t >> 5) + 8 * pass)) << 2;
        float4 vv = *(const float4*)(kv + ((size_t)(b*NA + r)) * (2*DM) + DM + h*HD + c4);
        Vt[(c4+0) * GVS + r] = vv.x;
        Vt[(c4+1) * GVS + r] = vv.y;
        Vt[(c4+2) * GVS + r] = vv.z;
        Vt[(c4+3) * GVS + r] = vv.w;
    }
    __syncthreads();

    const int warp = t >> 5, lane = t & 31;
    for (int iq = warp * 8; iq < warp * 8 + 8; iq++) {
        const float4* qr4 = (const float4*)(Qs + iq * GQS);
        const float4* kr4 = (const float4*)(Ks + lane * GQS);
        float s = 0.f;
#pragma unroll
        for (int d = 0; d < 16; d++) {
            float4 q4 = qr4[d], k4 = kr4[d];
            s += q4.x*k4.x + q4.y*k4.y + q4.z*k4.z + q4.w*k4.w;
        }
        s *= 0.125f;
        float smax = s;
#pragma unroll
        for (int o = 16; o; o >>= 1) smax = fmaxf(smax, __shfl_xor_sync(0xffffffffu, smax, o));
        float e = expf(s - smax);
        float ssum = e;
#pragma unroll
        for (int o = 16; o; o >>= 1) ssum += __shfl_xor_sync(0xffffffffu, ssum, o);
        Pb[warp][lane] = e;
        __syncwarp();

        float o0 = 0.f, o1 = 0.f;
        const float* va = Vt + lane * GVS;
        const float* vb = Vt + (lane + 32) * GVS;
#pragma unroll
        for (int j4 = 0; j4 < 32; j4 += 4) {
            float4 p  = *(const float4*)(&Pb[warp][j4]);
            float4 a4 = *(const float4*)(va + j4);
            float4 b4 = *(const float4*)(vb + j4);
            o0 += p.x*a4.x + p.y*a4.y + p.z*a4.z + p.w*a4.w;
            o1 += p.x*b4.x + p.y*b4.y + p.z*b4.z + p.w*b4.w;
        }
        const float inv = 1.0f / ssum;
        __half* dst = outh + ((size_t)(b*SEQ + q0 + iq)) * DM + h*HD;
        dst[lane]      = __float2half_rn(o0 * inv);
        dst[lane + 32] = __float2half_rn(o1 * inv);
        __syncwarp();
    }
}

// ---------------- layernorm (optional fp16 copy) ----------------
__global__ __launch_bounds__(128)
void ln_kernel(const float* __restrict__ x, const float* __restrict__ g,
               const float* __restrict__ be, float* __restrict__ out,
               __half* __restrict__ outh)
{
    __shared__ float red[8];
    const int row = blockIdx.x;
    const int t = threadIdx.x;
    float4 v = ((const float4*)(x + (size_t)row * DM))[t];
    float s  = v.x + v.y + v.z + v.w;
    float ss = v.x*v.x + v.y*v.y + v.z*v.z + v.w*v.w;
#pragma unroll
    for (int o = 16; o; o >>= 1) {
        s  += __shfl_xor_sync(0xffffffffu, s, o);
        ss += __shfl_xor_sync(0xffffffffu, ss, o);
    }
    const int warp = t >> 5, lane = t & 31;
    if (lane == 0) { red[warp] = s; red[warp + 4] = ss; }
    __syncthreads();
    if (t == 0) {
        red[0] = red[0] + red[1] + red[2] + red[3];
        red[4] = red[4] + red[5] + red[6] + red[7];
    }
    __syncthreads();
    float mu  = red[0] * (1.0f / DM);
    float var = red[4] * (1.0f / DM) - mu * mu;
    float inv = rsqrtf(var + 1e-5f);
    float4 gg = ((const float4*)g)[t];
    float4 bb = ((const float4*)be)[t];
    float4 o;
    o.x = (v.x - mu) * inv * gg.x + bb.x;
    o.y = (v.y - mu) * inv * gg.y + bb.y;
    o.z = (v.z - mu) * inv * gg.z + bb.z;
    o.w = (v.w - mu) * inv * gg.w + bb.w;
    ((float4*)(out + (size_t)row * DM))[t] = o;
    if (outh) {
        __half2* dh = (__half2*)(outh + (size_t)row * DM) + t * 2;
        dh[0] = __floats2half2_rn(o.x, o.y);
        dh[1] = __floats2half2_rn(o.z, o.w);
    }
}

// ---------------- launch ----------------
extern "C" void kernel_launch(void* const* d_in, const int* in_sizes, int n_in,
                              void* d_out, int out_size)
{
    const float* x      = (const float*)d_in[0];
    const float* anchors= (const float*)d_in[1];
    const float* lw_in  = (const float*)d_in[2];
    const float* lb_in  = (const float*)d_in[3];
    const float* lw_out = (const float*)d_in[4];
    const float* lb_out = (const float*)d_in[5];
    const float* gw_in  = (const float*)d_in[6];
    const float* gb_in  = (const float*)d_in[7];
    const float* gw_out = (const float*)d_in[8];
    const float* gb_out = (const float*)d_in[9];
    const float* w1     = (const float*)d_in[10];
    const float* b1     = (const float*)d_in[11];
    const float* w2     = (const float*)d_in[12];
    const float* b2     = (const float*)d_in[13];
    const float* g1     = (const float*)d_in[14];
    const float* be1    = (const float*)d_in[15];
    const float* g2     = (const float*)d_in[16];
    const float* be2    = (const float*)d_in[17];
    float* out = (float*)d_out;

    float *x1, *q2, *kv2, *x2, *x3;
    __half *wth, *xh, *anchh, *attnh, *x1h, *x3h, *hh, *qkvh;
    cudaGetSymbolAddress((void**)&x1,   g_x1);
    cudaGetSymbolAddress((void**)&q2,   g_q2);
    cudaGetSymbolAddress((void**)&kv2,  g_kv2);
    cudaGetSymbolAddress((void**)&x2,   g_x2);
    cudaGetSymbolAddress((void**)&x3,   g_x3);
    cudaGetSymbolAddress((void**)&wth,  g_wth);
    cudaGetSymbolAddress((void**)&xh,   g_xh);
    cudaGetSymbolAddress((void**)&anchh,g_anchh);
    cudaGetSymbolAddress((void**)&attnh,g_attnh);
    cudaGetSymbolAddress((void**)&x1h,  g_x1h);
    cudaGetSymbolAddress((void**)&x3h,  g_x3h);
    cudaGetSymbolAddress((void**)&hh,   g_hh);
    cudaGetSymbolAddress((void**)&qkvh, g_qkvh);

    const int gemm_smem = GEMM_SMEM_W * (int)sizeof(uint32_t);
    const int lah_smem  = LAH_SMEM_W * (int)sizeof(uint32_t);
    cudaFuncSetAttribute(local_attn_h, cudaFuncAttributeMaxDynamicSharedMemorySize, lah_smem);
    cudaFuncSetAttribute((const void*)gemm_hh<false,0>, cudaFuncAttributeMaxDynamicSharedMemorySize, gemm_smem);
    cudaFuncSetAttribute((const void*)gemm_hh<false,2>, cudaFuncAttributeMaxDynamicSharedMemorySize, gemm_smem);
    cudaFuncSetAttribute((const void*)gemm_hh<true,1>,  cudaFuncAttributeMaxDynamicSharedMemorySize, gemm_smem);
    cudaFuncSetAttribute((const void*)gemm_hh<false,1>, cudaFuncAttributeMaxDynamicSharedMemorySize, gemm_smem);

    dim3 thr(256);

    // [1] weights + anchors -> fp16
    cvt_all<<<(WTF_TOTAL + ANCH_N + 255) / 256, 256>>>(
        lw_in, lw_out, gw_in, gw_out, w1, w2, anchors, wth, anchh);
    // [2] x -> fp16
    cvt4<<<((MROWS * DM / 4) + 255) / 256, 256>>>(x, xh, MROWS * DM / 4);
    // [3] anchor k,v projection (f32 out)
    gemm_hh<false,0><<<dim3(1024/128, MAROWS/128), thr, gemm_smem>>>(
        anchh, wth + OFF_GWIN + 512*512, gb_in + 512, nullptr, kv2, nullptr, MAROWS, 2*DM, DM);
    // [4] local QKV projection (f16 out)   <-- ncu capture target
    gemm_hh<false,1><<<dim3(1536/128, MROWS/128), thr, gemm_smem>>>(
        xh, wth + OFF_LWIN, lb_in, nullptr, nullptr, qkvh, MROWS, 3*DM, DM);
    // [5] windowed causal attention (tensor core) -> fp16
    local_attn_h<<<dim3(SEQ/64, NH, BATCH), 128, lah_smem>>>(qkvh, attnh);
    // [6] local out-proj + residual(x) -> x1 (f32) + x1h (f16)
    gemm_hh<false,2><<<dim3(DM/128, MROWS/128), thr, gemm_smem>>>(
        attnh, wth + OFF_LWOUT, lb_out, x, x1, x1h, MROWS, DM, DM);
    // [7] global q projection of x1h (f32 out)
    gemm_hh<false,0><<<dim3(DM/128, MROWS/128), thr, gemm_smem>>>(
        x1h, wth + OFF_GWIN, gb_in, nullptr, q2, nullptr, MROWS, DM, DM);
    // [8] global attention -> fp16
    global_attn_kernel<<<dim3(SEQ/64, NH, BATCH), thr>>>(q2, kv2, attnh);
    // [9] global out-proj + residual(x1) -> x2 (f32)
    gemm_hh<false,0><<<dim3(DM/128, MROWS/128), thr, gemm_smem>>>(
        attnh, wth + OFF_GWOUT, gb_out, x1, x2, nullptr, MROWS, DM, DM);
    // [10] LN1 -> x3 (f32) + x3h (f16)
    ln_kernel<<<MROWS, 128>>>(x2, g1, be1, x3, x3h);
    // [11] FFN1 + exact GELU -> hh (f16 only)
    gemm_hh<true,1><<<dim3(FF/128, MROWS/128), thr, gemm_smem>>>(
        x3h, wth + OFF_W1, b1, nullptr, nullptr, hh, MROWS, FF, DM);
    // [12] FFN2 + residual(x3) -> x2 (f32)
    gemm_hh<false,0><<<dim3(DM/128, MROWS/128), thr, gemm_smem>>>(
        hh, wth + OFF_W2, b2, x3, x2, nullptr, MROWS, DM, FF);
    // [13] LN2 -> out
    ln_kernel<<<MROWS, 128>>>(x2, g2, be2, out, nullptr);
}

// round 16
// speedup vs baseline: 1.3345x; 1.1327x over previous
#include <cuda_runtime.h>
#include <cuda_fp16.h>
#include <math.h>
#include <stdint.h>

#define BATCH 64
#define SEQ   512
#define DM    512
#define NH    8
#define HD    64
#define WIN   64
#define NA    32
#define FF    2048
#define MROWS (BATCH*SEQ)     // 32768
#define MAROWS (BATCH*NA)     // 2048

// ---------------- scratch ----------------
__device__ float g_x1 [(size_t)MROWS * DM];
__device__ float g_x2 [(size_t)MROWS * DM];
__device__ float g_x3 [(size_t)MROWS * DM];
// fp16 buffers
__device__ __half g_qkvh [(size_t)MROWS * 3 * DM];
__device__ __half g_xh   [(size_t)MROWS * DM];
__device__ __half g_anchh[(size_t)MAROWS * DM];
__device__ __half g_attnh[(size_t)MROWS * DM];
__device__ __half g_x1h  [(size_t)MROWS * DM];
__device__ __half g_x3h  [(size_t)MROWS * DM];
__device__ __half g_hh   [(size_t)MROWS * FF];
__device__ __half g_q2h  [(size_t)MROWS * DM];
__device__ __half g_kv2h [(size_t)MAROWS * 2 * DM];
// fp16 weights, packed
#define SZ_LWIN  786432
#define SZ_LWOUT 262144
#define SZ_GWIN  786432
#define SZ_GWOUT 262144
#define SZ_W1    1048576
#define SZ_W2    1048576
#define OFF_LWIN  0
#define OFF_LWOUT (OFF_LWIN + SZ_LWIN)
#define OFF_GWIN  (OFF_LWOUT + SZ_LWOUT)
#define OFF_GWOUT (OFF_GWIN + SZ_GWIN)
#define OFF_W1    (OFF_GWOUT + SZ_GWOUT)
#define OFF_W2    (OFF_W1 + SZ_W1)
#define WTF_TOTAL (OFF_W2 + SZ_W2)
#define ANCH_N    (MAROWS * DM)
__device__ __half g_wth[(size_t)WTF_TOTAL];

// ================= helpers =================
__device__ __forceinline__ uint32_t smem_u32(const void* p) {
    uint32_t a;
    asm("{ .reg .u64 t; cvta.to.shared.u64 t, %1; cvt.u32.u64 %0, t; }" : "=r"(a) : "l"(p));
    return a;
}
__device__ __forceinline__ void mma16(float* c, const uint32_t* a, const uint32_t* b) {
    asm volatile(
        "mma.sync.aligned.m16n8k16.row.col.f32.f16.f16.f32 "
        "{%0,%1,%2,%3}, {%4,%5,%6,%7}, {%8,%9}, {%0,%1,%2,%3};"
        : "+f"(c[0]), "+f"(c[1]), "+f"(c[2]), "+f"(c[3])
        : "r"(a[0]), "r"(a[1]), "r"(a[2]), "r"(a[3]),
          "r"(b[0]), "r"(b[1]));
}
#define LDSM_X4(r0, r1, r2, r3, addr) \
    asm volatile("ldmatrix.sync.aligned.m8n8.x4.shared.b16 {%0,%1,%2,%3}, [%4];" \
        : "=r"(r0), "=r"(r1), "=r"(r2), "=r"(r3) : "r"(addr))
#define CP_ASYNC16(dst, src) \
    asm volatile("cp.async.cg.shared.global [%0], [%1], 16;" :: "r"(dst), "l"(src) : "memory")
#define CP_COMMIT() asm volatile("cp.async.commit_group;" ::: "memory")
#define CP_WAIT1()  asm volatile("cp.async.wait_group 1;" ::: "memory")

// ---------------- weight + anchor fp16 pre-convert (one launch) --------
__global__ __launch_bounds__(256)
void cvt_all(const float* __restrict__ lw_in, const float* __restrict__ lw_out,
             const float* __restrict__ gw_in, const float* __restrict__ gw_out,
             const float* __restrict__ w1, const float* __restrict__ w2,
             const float* __restrict__ anch,
             __half* __restrict__ dst, __half* __restrict__ anch_h)
{
    int i = blockIdx.x * 256 + threadIdx.x;
    if (i >= WTF_TOTAL + ANCH_N) return;
    if (i >= WTF_TOTAL) {
        anch_h[i - WTF_TOTAL] = __float2half_rn(anch[i - WTF_TOTAL]);
        return;
    }
    const float* src;
    int local;
    if      (i < OFF_LWOUT) { src = lw_in;  local = i - OFF_LWIN; }
    else if (i < OFF_GWIN)  { src = lw_out; local = i - OFF_LWOUT; }
    else if (i < OFF_GWOUT) { src = gw_in;  local = i - OFF_GWIN; }
    else if (i < OFF_W1)    { src = gw_out; local = i - OFF_GWOUT; }
    else if (i < OFF_W2)    { src = w1;     local = i - OFF_W1; }
    else                    { src = w2;     local = i - OFF_W2; }
    dst[i] = __float2half_rn(src[local]);
}

// ---------------- vectorized f32 -> f16 (for x) ----------------
__global__ __launch_bounds__(256)
void cvt4(const float* __restrict__ src, __half* __restrict__ dst, int n4)
{
    int i = blockIdx.x * 256 + threadIdx.x;
    if (i < n4) {
        float4 v = ((const float4*)src)[i];
        ((__half2*)dst)[i * 2]     = __floats2half2_rn(v.x, v.y);
        ((__half2*)dst)[i * 2 + 1] = __floats2half2_rn(v.z, v.w);
    }
}

// ================= fp16 GEMM: 3-stage cp.async pipeline (passing) ===========
#define ROWW 36
#define TILE_W (128 * ROWW)
#define GEMM_SMEM_W (6 * TILE_W)

template<bool GELU, int OMODE>
__global__ __launch_bounds__(256, 2)
void gemm_hh(const __half* __restrict__ A, const __half* __restrict__ W,
             const float* __restrict__ bias, const float* __restrict__ res,
             float* __restrict__ C, __half* __restrict__ Ch, int M, int N, int K)
{
    extern __shared__ uint32_t smh[];
    const uint32_t smb = smem_u32(smh);

    const int t = threadIdx.x;
    const int wid = t >> 5, lane = t & 31;
    const int gid = lane >> 2, tig = lane & 3;
    const int wm = wid >> 2;
    const int wn = wid & 3;
    const int bm = blockIdx.y * 128;
    const int bn = blockIdx.x * 128;

    const int ar = t >> 3;
    const int ac8 = (t & 7) * 8;
    const __half* Abase = A + (size_t)(bm + ar) * K + ac8;
    const __half* Wbase = W + (size_t)(bn + ar) * K + ac8;
    const uint32_t stoff = (uint32_t)(ar * ROWW + (t & 7) * 4) * 4u;

    const int a_r = lane & 15, a_k4 = (lane >> 4) * 4;
    uint32_t aOff[4];
#pragma unroll
    for (int i = 0; i < 4; i++)
        aOff[i] = (uint32_t)((wm * 64 + i * 16 + a_r) * ROWW + a_k4) * 4u;
    const int b_r = lane & 7, b_sel = (lane >> 4) & 1, b_k4 = ((lane >> 3) & 1) * 4;
    uint32_t bOff[2];
#pragma unroll
    for (int jj = 0; jj < 2; jj++)
        bOff[jj] = (uint32_t)((wn * 32 + (jj * 2 + b_sel) * 8 + b_r) * ROWW + b_k4) * 4u;

    float acc[4][4][4];
#pragma unroll
    for (int i = 0; i < 4; i++)
#pragma unroll
        for (int j = 0; j < 4; j++)
#pragma unroll
            for (int q = 0; q < 4; q++) acc[i][j][q] = 0.f;

    const int KT = K >> 6;

#pragma unroll
    for (int s = 0; s < 2; s++) {
        const __half* Ap = Abase + (size_t)s * 64;
        const __half* Wp = Wbase + (size_t)s * 64;
        uint32_t adst = smb + (uint32_t)(s * TILE_W) * 4u + stoff;
        uint32_t bdst = smb + (uint32_t)((3 + s) * TILE_W) * 4u + stoff;
#pragma unroll
        for (int i = 0; i < 4; i++) {
            CP_ASYNC16(adst + (uint32_t)(i * 32 * ROWW * 4), Ap + (size_t)(i * 32) * K);
            CP_ASYNC16(bdst + (uint32_t)(i * 32 * ROWW * 4), Wp + (size_t)(i * 32) * K);
        }
        CP_COMMIT();
    }

    int stage = 0;
    for (int kt = 0; kt < KT; kt++) {
        CP_WAIT1();
        __syncthreads();

        if (kt + 2 < KT) {
            int s2 = stage + 2;
            if (s2 >= 3) s2 -= 3;
            const __half* Ap = Abase + (size_t)(kt + 2) * 64;
            const __half* Wp = Wbase + (size_t)(kt + 2) * 64;
            uint32_t adst = smb + (uint32_t)(s2 * TILE_W) * 4u + stoff;
            uint32_t bdst = smb + (uint32_t)((3 + s2) * TILE_W) * 4u + stoff;
#pragma unroll
            for (int i = 0; i < 4; i++) {
                CP_ASYNC16(adst + (uint32_t)(i * 32 * ROWW * 4), Ap + (size_t)(i * 32) * K);
                CP_ASYNC16(bdst + (uint32_t)(i * 32 * ROWW * 4), Wp + (size_t)(i * 32) * K);
            }
            CP_COMMIT();
        } else {
            CP_COMMIT();
        }

        const uint32_t aBase = smb + (uint32_t)(stage * TILE_W) * 4u;
        const uint32_t bBase = smb + (uint32_t)((3 + stage) * TILE_W) * 4u;
#pragma unroll
        for (int kk = 0; kk < 4; kk++) {
            uint32_t a[4][4], b[4][2];
#pragma unroll
            for (int i = 0; i < 4; i++)
                LDSM_X4(a[i][0], a[i][1], a[i][2], a[i][3],
                        aBase + aOff[i] + (uint32_t)(kk * 32));
#pragma unroll
            for (int jj = 0; jj < 2; jj++)
                LDSM_X4(b[jj*2][0], b[jj*2][1], b[jj*2+1][0], b[jj*2+1][1],
                        bBase + bOff[jj] + (uint32_t)(kk * 32));
#pragma unroll
            for (int i = 0; i < 4; i++)
#pragma unroll
                for (int j = 0; j < 4; j++)
                    mma16(acc[i][j], a[i], b[j]);
        }

        stage = (stage == 2) ? 0 : (stage + 1);
    }

#pragma unroll
    for (int j = 0; j < 4; j++) {
        const int gc = bn + wn * 32 + j * 8 + 2 * tig;
        const float2 bia = *(const float2*)(bias + gc);
#pragma unroll
        for (int i = 0; i < 4; i++) {
            const int gr = bm + wm * 64 + i * 16 + gid;
            float2 v0, v1;
            v0.x = acc[i][j][0] + bia.x; v0.y = acc[i][j][1] + bia.y;
            v1.x = acc[i][j][2] + bia.x; v1.y = acc[i][j][3] + bia.y;
            if (res) {
                float2 r0 = *(const float2*)(res + (size_t)gr * N + gc);
                float2 r1 = *(const float2*)(res + (size_t)(gr + 8) * N + gc);
                v0.x += r0.x; v0.y += r0.y; v1.x += r1.x; v1.y += r1.y;
            }
            if (GELU) {
                v0.x = 0.5f * v0.x * (1.0f + erff(v0.x * 0.70710678118654752f));
                v0.y = 0.5f * v0.y * (1.0f + erff(v0.y * 0.70710678118654752f));
                v1.x = 0.5f * v1.x * (1.0f + erff(v1.x * 0.70710678118654752f));
                v1.y = 0.5f * v1.y * (1.0f + erff(v1.y * 0.70710678118654752f));
            }
            if (OMODE != 1) {
                *(float2*)(C + (size_t)gr * N + gc) = v0;
                *(float2*)(C + (size_t)(gr + 8) * N + gc) = v1;
            }
            if (OMODE >= 1) {
                *(__half2*)(Ch + (size_t)gr * N + gc) = __floats2half2_rn(v0.x, v0.y);
                *(__half2*)(Ch + (size_t)(gr + 8) * N + gc) = __floats2half2_rn(v1.x, v1.y);
            }
        }
    }
}

// ================= local windowed causal attention — tensor core (passing) ===
#define AQS 36    // words per Q/K row (72 halves)
#define AVS 68    // words per Vt/P row (136 halves)
#define LAH_SMEM_W (64*AQS + 128*AQS + 64*AVS + 64*AVS)

__global__ __launch_bounds__(128, 3)
void local_attn_h(const __half* __restrict__ qkvh, __half* __restrict__ outh)
{
    extern __shared__ uint32_t smw[];
    __half* Qh = (__half*)smw;
    __half* Kh = Qh + 64 * (AQS * 2);
    __half* Vh = Kh + 128 * (AQS * 2);
    __half* Ph = Vh + 64 * (AVS * 2);
    const uint32_t smb = smem_u32(smw);
    const uint32_t qBase = smb;
    const uint32_t kBase = smb + 64u * AQS * 4u;
    const uint32_t vBase = kBase + 128u * AQS * 4u;
    const uint32_t pBase = vBase + 64u * AVS * 4u;

    const int qt = blockIdx.x, h = blockIdx.y, b = blockIdx.z;
    const int t = threadIdx.x;
    const int w = t >> 5, lane = t & 31;
    const int gid = lane >> 2, tig = lane & 3;
    const int q0 = qt * 64;
    const int kbase = q0 - 64;

    for (int idx = t; idx < 64 * 8; idx += 128) {
        int r = idx >> 3, c8 = (idx & 7) * 8;
        float4 v = *(const float4*)(qkvh + ((size_t)(b*SEQ + q0 + r)) * (3*DM) + h*HD + c8);
        *(float4*)(Qh + r * 72 + c8) = v;
    }
    for (int idx = t; idx < 128 * 8; idx += 128) {
        int r = idx >> 3, c8 = (idx & 7) * 8;
        int j = kbase + r;
        if (j >= 0) {
            float4 v = *(const float4*)(qkvh + ((size_t)(b*SEQ + j)) * (3*DM) + DM + h*HD + c8);
            *(float4*)(Kh + r * 72 + c8) = v;
        }
    }
    for (int idx = t; idx < 128 * 8; idx += 128) {
        int r = idx >> 3, c8 = (idx & 7) * 8;
        int j = kbase + r;
        __half vals[8];
        if (j >= 0) {
            *(float4*)vals = *(const float4*)(qkvh + ((size_t)(b*SEQ + j)) * (3*DM) + 2*DM + h*HD + c8);
        } else {
#pragma unroll
            for (int d = 0; d < 8; d++) vals[d] = __float2half_rn(0.f);
        }
#pragma unroll
        for (int d = 0; d < 8; d++) Vh[(c8 + d) * 136 + r] = vals[d];
    }
    __syncthreads();

    const int b_r = lane & 7, b_sel = (lane >> 4) & 1, b_k4 = ((lane >> 3) & 1) * 4;
    const uint32_t aOffQ = (uint32_t)((w * 16 + (lane & 15)) * AQS + (lane >> 4) * 4) * 4u;

    float sacc[16][4];
#pragma unroll
    for (int nt = 0; nt < 16; nt++)
#pragma unroll
        for (int q = 0; q < 4; q++) sacc[nt][q] = 0.f;

#pragma unroll
    for (int kk = 0; kk < 4; kk++) {
        uint32_t a[4];
        LDSM_X4(a[0], a[1], a[2], a[3], qBase + aOffQ + (uint32_t)(kk * 32));
#pragma unroll
        for (int jj = 0; jj < 8; jj++) {
            uint32_t bf[4];
            uint32_t baddr = kBase +
                (uint32_t)(((jj * 2 + b_sel) * 8 + b_r) * AQS + b_k4) * 4u + (uint32_t)(kk * 32);
            LDSM_X4(bf[0], bf[1], bf[2], bf[3], baddr);
            mma16(sacc[jj*2],     a, bf);
            mma16(sacc[jj*2 + 1], a, bf + 2);
        }
    }

    const int r0 = w * 16 + gid, r1 = r0 + 8;
    float mx0 = -1e30f, mx1 = -1e30f;
#pragma unroll
    for (int nt = 0; nt < 16; nt++) {
        const int c0 = nt * 8 + 2 * tig, c1 = c0 + 1;
        bool ok00 = (c0 >= r0) && (c0 <= r0 + 64) && (kbase + c0 >= 0);
        bool ok01 = (c1 >= r0) && (c1 <= r0 + 64) && (kbase + c1 >= 0);
        bool ok10 = (c0 >= r1) && (c0 <= r1 + 64) && (kbase + c0 >= 0);
        bool ok11 = (c1 >= r1) && (c1 <= r1 + 64) && (kbase + c1 >= 0);
        sacc[nt][0] = ok00 ? sacc[nt][0] * 0.125f : -1e30f;
        sacc[nt][1] = ok01 ? sacc[nt][1] * 0.125f : -1e30f;
        sacc[nt][2] = ok10 ? sacc[nt][2] * 0.125f : -1e30f;
        sacc[nt][3] = ok11 ? sacc[nt][3] * 0.125f : -1e30f;
        mx0 = fmaxf(mx0, fmaxf(sacc[nt][0], sacc[nt][1]));
        mx1 = fmaxf(mx1, fmaxf(sacc[nt][2], sacc[nt][3]));
    }
#pragma unroll
    for (int o = 1; o <= 2; o <<= 1) {
        mx0 = fmaxf(mx0, __shfl_xor_sync(0xffffffffu, mx0, o));
        mx1 = fmaxf(mx1, __shfl_xor_sync(0xffffffffu, mx1, o));
    }
    float sum0 = 0.f, sum1 = 0.f;
#pragma unroll
    for (int nt = 0; nt < 16; nt++) {
        float e00 = expf(sacc[nt][0] - mx0);
        float e01 = expf(sacc[nt][1] - mx0);
        float e10 = expf(sacc[nt][2] - mx1);
        float e11 = expf(sacc[nt][3] - mx1);
        sum0 += e00 + e01;
        sum1 += e10 + e11;
        *(__half2*)(Ph + r0 * 136 + nt * 8 + 2 * tig) = __floats2half2_rn(e00, e01);
        *(__half2*)(Ph + r1 * 136 + nt * 8 + 2 * tig) = __floats2half2_rn(e10, e11);
    }
#pragma unroll
    for (int o = 1; o <= 2; o <<= 1) {
        sum0 += __shfl_xor_sync(0xffffffffu, sum0, o);
        sum1 += __shfl_xor_sync(0xffffffffu, sum1, o);
    }
    const float inv0 = 1.0f / sum0, inv1 = 1.0f / sum1;
    __syncwarp();

    const uint32_t aOffP = (uint32_t)((w * 16 + (lane & 15)) * AVS + (lane >> 4) * 4) * 4u;
    float oacc[8][4];
#pragma unroll
    for (int nt = 0; nt < 8; nt++)
#pragma unroll
        for (int q = 0; q < 4; q++) oacc[nt][q] = 0.f;

#pragma unroll
    for (int kk = 0; kk < 8; kk++) {
        uint32_t a[4];
        LDSM_X4(a[0], a[1], a[2], a[3], pBase + aOffP + (uint32_t)(kk * 32));
#pragma unroll
        for (int jj = 0; jj < 4; jj++) {
            uint32_t bf[4];
            uint32_t baddr = vBase +
                (uint32_t)(((jj * 2 + b_sel) * 8 + b_r) * AVS + b_k4) * 4u + (uint32_t)(kk * 32);
            LDSM_X4(bf[0], bf[1], bf[2], bf[3], baddr);
            mma16(oacc[jj*2],     a, bf);
            mma16(oacc[jj*2 + 1], a, bf + 2);
        }
    }

#pragma unroll
    for (int nt = 0; nt < 8; nt++) {
        const int gc = h * HD + nt * 8 + 2 * tig;
        *(__half2*)(outh + (size_t)(b*SEQ + q0 + r0) * DM + gc) =
            __floats2half2_rn(oacc[nt][0] * inv0, oacc[nt][1] * inv0);
        *(__half2*)(outh + (size_t)(b*SEQ + q0 + r1) * DM + gc) =
            __floats2half2_rn(oacc[nt][2] * inv1, oacc[nt][3] * inv1);
    }
}

// ================= global attention vs anchors — tensor core fp16 ============
// S = Q@K^T (M=64,N=32,K=64); softmax (no mask); O = P@V (M=64,N=64,K=32).
// Vt/P row stride 40 halves (20 words): banks 20r+c mod 32 distinct -> conflict-free.
#define GVW 20
__global__ __launch_bounds__(128, 4)
void global_attn_h(const __half* __restrict__ q2h, const __half* __restrict__ kv2h,
                   __half* __restrict__ outh)
{
    __shared__ __align__(16) __half Qh[64 * 72];
    __shared__ __align__(16) __half Kh[32 * 72];
    __shared__ __align__(16) __half Vh[64 * 40];   // dim-major [dim][key]
    __shared__ __align__(16) __half Ph[64 * 40];

    const uint32_t qBase = smem_u32(Qh);
    const uint32_t kBase = smem_u32(Kh);
    const uint32_t vBase = smem_u32(Vh);
    const uint32_t pBase = smem_u32(Ph);

    const int qt = blockIdx.x, h = blockIdx.y, b = blockIdx.z;
    const int t = threadIdx.x;
    const int w = t >> 5, lane = t & 31;
    const int gid = lane >> 2, tig = lane & 3;
    const int q0 = qt * 64;

    for (int idx = t; idx < 64 * 8; idx += 128) {
        int r = idx >> 3, c8 = (idx & 7) * 8;
        float4 v = *(const float4*)(q2h + ((size_t)(b*SEQ + q0 + r)) * DM + h*HD + c8);
        *(float4*)(Qh + r * 72 + c8) = v;
    }
    for (int idx = t; idx < 32 * 8; idx += 128) {
        int r = idx >> 3, c8 = (idx & 7) * 8;
        float4 v = *(const float4*)(kv2h + ((size_t)(b*NA + r)) * (2*DM) + h*HD + c8);
        *(float4*)(Kh + r * 72 + c8) = v;
    }
    for (int idx = t; idx < 32 * 8; idx += 128) {
        int r = idx >> 3, c8 = (idx & 7) * 8;   // r = key, c8 = dim chunk
        __half vals[8];
        *(float4*)vals = *(const float4*)(kv2h + ((size_t)(b*NA + r)) * (2*DM) + DM + h*HD + c8);
#pragma unroll
        for (int d = 0; d < 8; d++) Vh[(c8 + d) * 40 + r] = vals[d];
    }
    __syncthreads();

    const int b_r = lane & 7, b_sel = (lane >> 4) & 1, b_k4 = ((lane >> 3) & 1) * 4;
    const uint32_t aOffQ = (uint32_t)((w * 16 + (lane & 15)) * AQS + (lane >> 4) * 4) * 4u;

    // ---- S = Q @ K^T (N=32 -> 4 n-tiles, 2 LDSM groups) ----
    float sacc[4][4];
#pragma unroll
    for (int nt = 0; nt < 4; nt++)
#pragma unroll
        for (int q = 0; q < 4; q++) sacc[nt][q] = 0.f;

#pragma unroll
    for (int kk = 0; kk < 4; kk++) {
        uint32_t a[4];
        LDSM_X4(a[0], a[1], a[2], a[3], qBase + aOffQ + (uint32_t)(kk * 32));
#pragma unroll
        for (int jj = 0; jj < 2; jj++) {
            uint32_t bf[4];
            uint32_t baddr = kBase +
                (uint32_t)(((jj * 2 + b_sel) * 8 + b_r) * AQS + b_k4) * 4u + (uint32_t)(kk * 32);
            LDSM_X4(bf[0], bf[1], bf[2], bf[3], baddr);
            mma16(sacc[jj*2],     a, bf);
            mma16(sacc[jj*2 + 1], a, bf + 2);
        }
    }

    // ---- softmax over 32 cols (no mask) ----
    const int r0 = w * 16 + gid, r1 = r0 + 8;
    float mx0 = -1e30f, mx1 = -1e30f;
#pragma unroll
    for (int nt = 0; nt < 4; nt++) {
        sacc[nt][0] *= 0.125f; sacc[nt][1] *= 0.125f;
        sacc[nt][2] *= 0.125f; sacc[nt][3] *= 0.125f;
        mx0 = fmaxf(mx0, fmaxf(sacc[nt][0], sacc[nt][1]));
        mx1 = fmaxf(mx1, fmaxf(sacc[nt][2], sacc[nt][3]));
    }
#pragma unroll
    for (int o = 1; o <= 2; o <<= 1) {
        mx0 = fmaxf(mx0, __shfl_xor_sync(0xffffffffu, mx0, o));
        mx1 = fmaxf(mx1, __shfl_xor_sync(0xffffffffu, mx1, o));
    }
    float sum0 = 0.f, sum1 = 0.f;
#pragma unroll
    for (int nt = 0; nt < 4; nt++) {
        float e00 = expf(sacc[nt][0] - mx0);
        float e01 = expf(sacc[nt][1] - mx0);
        float e10 = expf(sacc[nt][2] - mx1);
        float e11 = expf(sacc[nt][3] - mx1);
        sum0 += e00 + e01;
        sum1 += e10 + e11;
        *(__half2*)(Ph + r0 * 40 + nt * 8 + 2 * tig) = __floats2half2_rn(e00, e01);
        *(__half2*)(Ph + r1 * 40 + nt * 8 + 2 * tig) = __floats2half2_rn(e10, e11);
    }
#pragma unroll
    for (int o = 1; o <= 2; o <<= 1) {
        sum0 += __shfl_xor_sync(0xffffffffu, sum0, o);
        sum1 += __shfl_xor_sync(0xffffffffu, sum1, o);
    }
    const float inv0 = 1.0f / sum0, inv1 = 1.0f / sum1;
    __syncwarp();

    // ---- O = P @ V (K=32 -> kk in {0,1}) ----
    const uint32_t aOffP = (uint32_t)((w * 16 + (lane & 15)) * GVW + (lane >> 4) * 4) * 4u;
    float oacc[8][4];
#pragma unroll
    for (int nt = 0; nt < 8; nt++)
#pragma unroll
        for (int q = 0; q < 4; q++) oacc[nt][q] = 0.f;

#pragma unroll
    for (int kk = 0; kk < 2; kk++) {
        uint32_t a[4];
        LDSM_X4(a[0], a[1], a[2], a[3], pBase + aOffP + (uint32_t)(kk * 32));
#pragma unroll
        for (int jj = 0; jj < 4; jj++) {
            uint32_t bf[4];
            uint32_t baddr = vBase +
                (uint32_t)(((jj * 2 + b_sel) * 8 + b_r) * GVW + b_k4) * 4u + (uint32_t)(kk * 32);
            LDSM_X4(bf[0], bf[1], bf[2], bf[3], baddr);
            mma16(oacc[jj*2],     a, bf);
            mma16(oacc[jj*2 + 1], a, bf + 2);
        }
    }

#pragma unroll
    for (int nt = 0; nt < 8; nt++) {
        const int gc = h * HD + nt * 8 + 2 * tig;
        *(__half2*)(outh + (size_t)(b*SEQ + q0 + r0) * DM + gc) =
            __floats2half2_rn(oacc[nt][0] * inv0, oacc[nt][1] * inv0);
        *(__half2*)(outh + (size_t)(b*SEQ + q0 + r1) * DM + gc) =
            __floats2half2_rn(oacc[nt][2] * inv1, oacc[nt][3] * inv1);
    }
}

// ---------------- layernorm (optional fp16 copy) ----------------
__global__ __launch_bounds__(128)
void ln_kernel(const float* __restrict__ x, const float* __restrict__ g,
               const float* __restrict__ be, float* __restrict__ out,
               __half* __restrict__ outh)
{
    __shared__ float red[8];
    const int row = blockIdx.x;
    const int t = threadIdx.x;
    float4 v = ((const float4*)(x + (size_t)row * DM))[t];
    float s  = v.x + v.y + v.z + v.w;
    float ss = v.x*v.x + v.y*v.y + v.z*v.z + v.w*v.w;
#pragma unroll
    for (int o = 16; o; o >>= 1) {
        s  += __shfl_xor_sync(0xffffffffu, s, o);
        ss += __shfl_xor_sync(0xffffffffu, ss, o);
    }
    const int warp = t >> 5, lane = t & 31;
    if (lane == 0) { red[warp] = s; red[warp + 4] = ss; }
    __syncthreads();
    if (t == 0) {
        red[0] = red[0] + red[1] + red[2] + red[3];
        red[4] = red[4] + red[5] + red[6] + red[7];
    }
    __syncthreads();
    float mu  = red[0] * (1.0f / DM);
    float var = red[4] * (1.0f / DM) - mu * mu;
    float inv = rsqrtf(var + 1e-5f);
    float4 gg = ((const float4*)g)[t];
    float4 bb = ((const float4*)be)[t];
    float4 o;
    o.x = (v.x - mu) * inv * gg.x + bb.x;
    o.y = (v.y - mu) * inv * gg.y + bb.y;
    o.z = (v.z - mu) * inv * gg.z + bb.z;
    o.w = (v.w - mu) * inv * gg.w + bb.w;
    ((float4*)(out + (size_t)row * DM))[t] = o;
    if (outh) {
        __half2* dh = (__half2*)(outh + (size_t)row * DM) + t * 2;
        dh[0] = __floats2half2_rn(o.x, o.y);
        dh[1] = __floats2half2_rn(o.z, o.w);
    }
}

// ---------------- launch ----------------
extern "C" void kernel_launch(void* const* d_in, const int* in_sizes, int n_in,
                              void* d_out, int out_size)
{
    const float* x      = (const float*)d_in[0];
    const float* anchors= (const float*)d_in[1];
    const float* lw_in  = (const float*)d_in[2];
    const float* lb_in  = (const float*)d_in[3];
    const float* lw_out = (const float*)d_in[4];
    const float* lb_out = (const float*)d_in[5];
    const float* gw_in  = (const float*)d_in[6];
    const float* gb_in  = (const float*)d_in[7];
    const float* gw_out = (const float*)d_in[8];
    const float* gb_out = (const float*)d_in[9];
    const float* w1     = (const float*)d_in[10];
    const float* b1     = (const float*)d_in[11];
    const float* w2     = (const float*)d_in[12];
    const float* b2     = (const float*)d_in[13];
    const float* g1     = (const float*)d_in[14];
    const float* be1    = (const float*)d_in[15];
    const float* g2     = (const float*)d_in[16];
    const float* be2    = (const float*)d_in[17];
    float* out = (float*)d_out;

    float *x1, *x2, *x3;
    __half *wth, *xh, *anchh, *attnh, *x1h, *x3h, *hh, *qkvh, *q2h, *kv2h;
    cudaGetSymbolAddress((void**)&x1,   g_x1);
    cudaGetSymbolAddress((void**)&x2,   g_x2);
    cudaGetSymbolAddress((void**)&x3,   g_x3);
    cudaGetSymbolAddress((void**)&wth,  g_wth);
    cudaGetSymbolAddress((void**)&xh,   g_xh);
    cudaGetSymbolAddress((void**)&anchh,g_anchh);
    cudaGetSymbolAddress((void**)&attnh,g_attnh);
    cudaGetSymbolAddress((void**)&x1h,  g_x1h);
    cudaGetSymbolAddress((void**)&x3h,  g_x3h);
    cudaGetSymbolAddress((void**)&hh,   g_hh);
    cudaGetSymbolAddress((void**)&qkvh, g_qkvh);
    cudaGetSymbolAddress((void**)&q2h,  g_q2h);
    cudaGetSymbolAddress((void**)&kv2h, g_kv2h);

    const int gemm_smem = GEMM_SMEM_W * (int)sizeof(uint32_t);
    const int lah_smem  = LAH_SMEM_W * (int)sizeof(uint32_t);
    cudaFuncSetAttribute(local_attn_h, cudaFuncAttributeMaxDynamicSharedMemorySize, lah_smem);
    cudaFuncSetAttribute((const void*)gemm_hh<false,0>, cudaFuncAttributeMaxDynamicSharedMemorySize, gemm_smem);
    cudaFuncSetAttribute((const void*)gemm_hh<false,2>, cudaFuncAttributeMaxDynamicSharedMemorySize, gemm_smem);
    cudaFuncSetAttribute((const void*)gemm_hh<true,1>,  cudaFuncAttributeMaxDynamicSharedMemorySize, gemm_smem);
    cudaFuncSetAttribute((const void*)gemm_hh<false,1>, cudaFuncAttributeMaxDynamicSharedMemorySize, gemm_smem);

    dim3 thr(256);

    // [1] weights + anchors -> fp16
    cvt_all<<<(WTF_TOTAL + ANCH_N + 255) / 256, 256>>>(
        lw_in, lw_out, gw_in, gw_out, w1, w2, anchors, wth, anchh);
    // [2] x -> fp16
    cvt4<<<((MROWS * DM / 4) + 255) / 256, 256>>>(x, xh, MROWS * DM / 4);
    // [3] anchor k,v projection (f16 out)
    gemm_hh<false,1><<<dim3(1024/128, MAROWS/128), thr, gemm_smem>>>(
        anchh, wth + OFF_GWIN + 512*512, gb_in + 512, nullptr, nullptr, kv2h, MAROWS, 2*DM, DM);
    // [4] local QKV projection (f16 out)
    gemm_hh<false,1><<<dim3(1536/128, MROWS/128), thr, gemm_smem>>>(
        xh, wth + OFF_LWIN, lb_in, nullptr, nullptr, qkvh, MROWS, 3*DM, DM);
    // [5] windowed causal attention (tensor core) -> fp16
    local_attn_h<<<dim3(SEQ/64, NH, BATCH), 128, lah_smem>>>(qkvh, attnh);
    // [6] local out-proj + residual(x) -> x1 (f32) + x1h (f16)
    gemm_hh<false,2><<<dim3(DM/128, MROWS/128), thr, gemm_smem>>>(
        attnh, wth + OFF_LWOUT, lb_out, x, x1, x1h, MROWS, DM, DM);
    // [7] global q projection of x1h (f16 out)
    gemm_hh<false,1><<<dim3(DM/128, MROWS/128), thr, gemm_smem>>>(
        x1h, wth + OFF_GWIN, gb_in, nullptr, nullptr, q2h, MROWS, DM, DM);
    // [8] global attention (tensor core) -> fp16
    global_attn_h<<<dim3(SEQ/64, NH, BATCH), 128>>>(q2h, kv2h, attnh);
    // [9] global out-proj + residual(x1) -> x2 (f32)
    gemm_hh<false,0><<<dim3(DM/128, MROWS/128), thr, gemm_smem>>>(
        attnh, wth + OFF_GWOUT, gb_out, x1, x2, nullptr, MROWS, DM, DM);
    // [10] LN1 -> x3 (f32) + x3h (f16)
    ln_kernel<<<MROWS, 128>>>(x2, g1, be1, x3, x3h);
    // [11] FFN1 + exact GELU -> hh (f16 only)
    gemm_hh<true,1><<<dim3(FF/128, MROWS/128), thr, gemm_smem>>>(
        x3h, wth + OFF_W1, b1, nullptr, nullptr, hh, MROWS, FF, DM);
    // [12] FFN2 + residual(x3) -> x2 (f32)
    gemm_hh<false,0><<<dim3(DM/128, MROWS/128), thr, gemm_smem>>>(
        hh, wth + OFF_W2, b2, x3, x2, nullptr, MROWS, DM, FF);
    // [13] LN2 -> out
    ln_kernel<<<MROWS, 128>>>(x2, g2, be2, out, nullptr);
}